// round 3
// baseline (speedup 1.0000x reference)
#include <cuda_runtime.h>
#include <cstdint>
#include <math.h>

#define S_T   12
#define NN    16384
#define EE    262144          // 2^18
#define D     128
#define BB    64
#define TT    3072            // S*N/B
#define ROWS  (S_T*NN)        // 196608

// ---- scratch (static device allocations; no runtime alloc allowed) ----
__device__ __align__(16) float g_support[(size_t)ROWS * D];     // ~100 MB
__device__ __align__(16) float g_acc[(size_t)ROWS * D];         // ~100 MB
__device__ __align__(16) float g_gx[(size_t)ROWS * 512];        // ~402 MB

// ============================================================
// K0: zero the scatter accumulator
// ============================================================
__global__ void zero_kernel() {
    size_t i = (size_t)blockIdx.x * blockDim.x + threadIdx.x;
    float4* p = (float4*)g_acc;
    p[i] = make_float4(0.f, 0.f, 0.f, 0.f);
}

// ============================================================
// K1: support = xs @ gcn_weight   (196608x128 @ 128x128)
// tile: 64 rows x 128 cols, 256 threads, thread = (r, 32 cols)
// ============================================================
__global__ void support_kernel(const float* __restrict__ X,
                               const float* __restrict__ W) {
    extern __shared__ float sW[];            // [128][132] padded
    int tid = threadIdx.x;
    for (int idx = tid; idx < 128 * 128; idx += 256) {
        int k = idx >> 7, c = idx & 127;
        sW[k * 132 + c] = W[idx];            // W is [DIN][DOUT], direct
    }
    __syncthreads();

    int r = tid & 63, cg = tid >> 6;
    size_t row = (size_t)blockIdx.x * 64 + r;
    const float* xrow = X + row * 128;

    float acc[32];
#pragma unroll
    for (int i = 0; i < 32; ++i) acc[i] = 0.f;

    for (int k = 0; k < 128; k += 4) {
        float4 xv = *(const float4*)(xrow + k);
#pragma unroll
        for (int kk = 0; kk < 4; ++kk) {
            float xs_ = (&xv.x)[kk];
            const float4* wr = (const float4*)(sW + (size_t)(k + kk) * 132 + cg * 32);
#pragma unroll
            for (int c4 = 0; c4 < 8; ++c4) {
                float4 w = wr[c4];
                acc[c4*4+0] += xs_ * w.x;
                acc[c4*4+1] += xs_ * w.y;
                acc[c4*4+2] += xs_ * w.z;
                acc[c4*4+3] += xs_ * w.w;
            }
        }
    }
    float* yrow = g_support + row * 128 + cg * 32;
#pragma unroll
    for (int c4 = 0; c4 < 8; ++c4)
        *(float4*)(yrow + c4*4) = make_float4(acc[c4*4], acc[c4*4+1], acc[c4*4+2], acc[c4*4+3]);
}

// ============================================================
// K2: edge scatter — one warp per edge.
// acc[s][dst] += vals[s][e] * support[s][src]
// ============================================================
__global__ void scatter_kernel(const int* __restrict__ adj_idx,
                               const float* __restrict__ adj_val) {
    int wid  = (int)((blockIdx.x * (size_t)blockDim.x + threadIdx.x) >> 5);
    int lane = threadIdx.x & 31;
    int s = wid >> 18;                 // E = 2^18
    int e = wid & (EE - 1);

    const int* ib = adj_idx + (size_t)s * 2 * EE;
    int dst = ib[e];
    int src = ib[EE + e];
    float v = adj_val[(size_t)s * EE + e];

    const float4* sp = (const float4*)(g_support + ((size_t)s * NN + src) * D);
    float* ap = g_acc + ((size_t)s * NN + dst) * D + lane * 4;
    float4 m = sp[lane];
    atomicAdd(ap + 0, v * m.x);
    atomicAdd(ap + 1, v * m.y);
    atomicAdd(ap + 2, v * m.z);
    atomicAdd(ap + 3, v * m.w);
}

// ============================================================
// K3: gates_x = relu(acc + gcn_bias) @ W_ih^T  (196608x512, K=128)
// grid (3072 row-blocks, 4 col-blocks of 128), 256 threads
// ============================================================
__global__ void gatesx_kernel(const float* __restrict__ wih,
                              const float* __restrict__ gcn_bias) {
    extern __shared__ float sm[];
    float* sW = sm;                       // [128][132], sW[k][c] = wih[cb*128+c][k]
    float* sB = sm + 128 * 132;           // [128]
    int tid = threadIdx.x;
    int cb  = blockIdx.y;

    for (int idx = tid; idx < 128 * 128; idx += 256) {
        int cl = idx >> 7, k = idx & 127;
        sW[k * 132 + cl] = wih[((size_t)(cb * 128 + cl)) * 128 + k];
    }
    if (tid < 128) sB[tid] = gcn_bias[tid];
    __syncthreads();

    int r = tid & 63, cg = tid >> 6;
    size_t row = (size_t)blockIdx.x * 64 + r;
    const float* xrow = g_acc + row * 128;

    float acc[32];
#pragma unroll
    for (int i = 0; i < 32; ++i) acc[i] = 0.f;

    for (int k = 0; k < 128; k += 4) {
        float4 xv = *(const float4*)(xrow + k);
        float4 bb = *(const float4*)(sB + k);
        xv.x = fmaxf(xv.x + bb.x, 0.f);
        xv.y = fmaxf(xv.y + bb.y, 0.f);
        xv.z = fmaxf(xv.z + bb.z, 0.f);
        xv.w = fmaxf(xv.w + bb.w, 0.f);
#pragma unroll
        for (int kk = 0; kk < 4; ++kk) {
            float xs_ = (&xv.x)[kk];
            const float4* wr = (const float4*)(sW + (size_t)(k + kk) * 132 + cg * 32);
#pragma unroll
            for (int c4 = 0; c4 < 8; ++c4) {
                float4 w = wr[c4];
                acc[c4*4+0] += xs_ * w.x;
                acc[c4*4+1] += xs_ * w.y;
                acc[c4*4+2] += xs_ * w.z;
                acc[c4*4+3] += xs_ * w.w;
            }
        }
    }
    float* yrow = g_gx + row * 512 + cb * 128 + cg * 32;
#pragma unroll
    for (int c4 = 0; c4 < 8; ++c4)
        *(float4*)(yrow + c4*4) = make_float4(acc[c4*4], acc[c4*4+1], acc[c4*4+2], acc[c4*4+3]);
}

// ============================================================
// K4: LSTM recurrence — one CTA per batch lane (B=64 lanes are
// independent chains). 512 threads: thread j computes gate
// pre-activation j (gate = j>>7, col = j&127) each step.
// W_hh split: k in [0,64) in smem (transposed [k][j]),
//             k in [64,128) register-resident (64 per thread).
// Only intra-CTA __syncthreads() — no cross-CTA communication.
// ============================================================
__global__ void __launch_bounds__(512, 1)
lstm_kernel(const float* __restrict__ whh,
            const float* __restrict__ bih, const float* __restrict__ bhh,
            const float* __restrict__ h0,  const float* __restrict__ c0,
            float* __restrict__ out) {
    extern __shared__ float sm[];
    float* sW = sm;                 // [64][512]: sW[k*512+j] = whh[j*128+k]
    float* sH = sm + 64 * 512;      // [128]
    float* sC = sH + 128;           // [128]
    float* sG = sC + 128;           // [512]

    int j = threadIdx.x;            // 0..511
    int b = blockIdx.x;             // 0..63

    // low-K weights -> smem, transposed
    for (int idx = j; idx < 64 * 512; idx += 512) {
        int k = idx >> 9, jj = idx & 511;
        sW[idx] = whh[(size_t)jj * 128 + k];
    }
    // high-K weights -> registers
    float wreg[64];
#pragma unroll
    for (int k = 0; k < 64; ++k) wreg[k] = whh[(size_t)j * 128 + 64 + k];

    if (j < 128) {
        sH[j] = h0[b * 128 + j];
        sC[j] = c0[b * 128 + j];
    }
    float bias = bih[j] + bhh[j];
    __syncthreads();

    const float* gx = g_gx + (size_t)b * 512;

    for (int t = 0; t < TT; ++t) {
        float acc = gx[(size_t)t * (64 * 512) + j] + bias;  // coalesced

        // k in [0,64): h from smem (broadcast), w from smem (conflict-free)
#pragma unroll 4
        for (int k = 0; k < 64; k += 4) {
            float4 hv = *(const float4*)(sH + k);
            acc += hv.x * sW[(k + 0) * 512 + j];
            acc += hv.y * sW[(k + 1) * 512 + j];
            acc += hv.z * sW[(k + 2) * 512 + j];
            acc += hv.w * sW[(k + 3) * 512 + j];
        }
        // k in [64,128): h from smem (broadcast), w from registers
#pragma unroll
        for (int k = 0; k < 64; k += 4) {
            float4 hv = *(const float4*)(sH + 64 + k);
            acc += hv.x * wreg[k + 0];
            acc += hv.y * wreg[k + 1];
            acc += hv.z * wreg[k + 2];
            acc += hv.w * wreg[k + 3];
        }
        sG[j] = acc;
        __syncthreads();

        if (j < 128) {
            float gi = sG[j], gf = sG[128 + j], gg = sG[256 + j], go = sG[384 + j];
            float si = 1.f / (1.f + expf(-gi));
            float sf = 1.f / (1.f + expf(-gf));
            float so = 1.f / (1.f + expf(-go));
            float c = sf * sC[j] + si * tanhf(gg);
            sC[j] = c;
            float h = so * tanhf(c);
            sH[j] = h;     // safe: all sH reads done before prior sync
            out[((size_t)t * 64 + b) * 128 + j] = h;
        }
        __syncthreads();
    }
}

// ============================================================
// launch
// ============================================================
extern "C" void kernel_launch(void* const* d_in, const int* in_sizes, int n_in,
                              void* d_out, int out_size) {
    const int*   adj_idx = (const int*)  d_in[0];
    const float* adj_val = (const float*)d_in[1];
    const float* xs      = (const float*)d_in[2];
    const float* gw      = (const float*)d_in[3];
    const float* gb      = (const float*)d_in[4];
    const float* wih     = (const float*)d_in[5];
    const float* whh     = (const float*)d_in[6];
    const float* bih     = (const float*)d_in[7];
    const float* bhh     = (const float*)d_in[8];
    const float* h0      = (const float*)d_in[9];
    const float* c0      = (const float*)d_in[10];
    float* out = (float*)d_out;

    (void)in_sizes; (void)n_in; (void)out_size;

    static bool attr_done = false;
    if (!attr_done) {
        cudaFuncSetAttribute(support_kernel, cudaFuncAttributeMaxDynamicSharedMemorySize, 128 * 132 * 4);
        cudaFuncSetAttribute(gatesx_kernel,  cudaFuncAttributeMaxDynamicSharedMemorySize, (128 * 132 + 128) * 4);
        cudaFuncSetAttribute(lstm_kernel,    cudaFuncAttributeMaxDynamicSharedMemorySize, (64 * 512 + 128 + 128 + 512) * 4);
        attr_done = true;
    }

    // zero acc: ROWS*D/4 float4 = 6,291,456 -> 24576 blocks
    zero_kernel<<<24576, 256>>>();

    // support GEMM: 196608 rows / 64 = 3072 blocks
    support_kernel<<<3072, 256, 128 * 132 * 4>>>(xs, gw);

    // scatter: 12*262144 warps, 8 warps/block = 393216 blocks
    scatter_kernel<<<393216, 256>>>(adj_idx, adj_val);

    // gates_x GEMM: (3072 row-blocks, 4 col-blocks)
    gatesx_kernel<<<dim3(3072, 4), 256, (128 * 132 + 128) * 4>>>(wih, gb);

    // recurrence: 64 independent chains, one CTA each
    lstm_kernel<<<64, 512, (64 * 512 + 128 + 128 + 512) * 4>>>(whh, bih, bhh, h0, c0, out);
}

// round 4
// speedup vs baseline: 1.7340x; 1.7340x over previous
#include <cuda_runtime.h>
#include <cstdint>
#include <math.h>

#define S_T   12
#define NN    16384
#define EE    262144          // 2^18
#define D     128
#define BB    64
#define TT    3072            // S*N/B
#define ROWS  (S_T*NN)        // 196608

// ---- scratch (static device allocations; no runtime alloc allowed) ----
__device__ __align__(16) float g_support[(size_t)ROWS * D];     // ~100 MB
__device__ __align__(16) float g_acc[(size_t)ROWS * D];         // ~100 MB
__device__ __align__(16) float g_gx[(size_t)ROWS * 512];        // ~402 MB

// ============================================================
// K0: zero the scatter accumulator
// ============================================================
__global__ void zero_kernel() {
    size_t i = (size_t)blockIdx.x * blockDim.x + threadIdx.x;
    float4* p = (float4*)g_acc;
    p[i] = make_float4(0.f, 0.f, 0.f, 0.f);
}

// ============================================================
// Register-tiled fp32 GEMM core: 128x128 block, 256 threads,
// 8x8 per thread in 2x2 fragments of float4 (conflict-free LDS).
// ============================================================
#define GEMM_FRAG_LOOP(As, Bs)                                              \
    _Pragma("unroll")                                                       \
    for (int k = 0; k < 64; ++k) {                                          \
        float4 a0 = *(const float4*)&As[k * 132 + ty * 4];                  \
        float4 a1 = *(const float4*)&As[k * 132 + 64 + ty * 4];             \
        float4 b0 = *(const float4*)&Bs[k * 132 + tx * 4];                  \
        float4 b1 = *(const float4*)&Bs[k * 132 + 64 + tx * 4];             \
        float af[8] = {a0.x,a0.y,a0.z,a0.w,a1.x,a1.y,a1.z,a1.w};            \
        float bf[8] = {b0.x,b0.y,b0.z,b0.w,b1.x,b1.y,b1.z,b1.w};            \
        _Pragma("unroll")                                                   \
        for (int i = 0; i < 8; ++i)                                         \
            _Pragma("unroll")                                               \
            for (int jj = 0; jj < 8; ++jj)                                  \
                acc[i][jj] += af[i] * bf[jj];                               \
    }

// ============================================================
// K1: support = xs @ gcn_weight   (196608x128 @ 128x128)
// ============================================================
__global__ void __launch_bounds__(256)
support_kernel(const float* __restrict__ X, const float* __restrict__ W) {
    extern __shared__ float sm[];
    float* As = sm;                 // [64][132]  (As[k][r])
    float* Bs = sm + 64 * 132;      // [64][132]  (Bs[k][c])

    int tid = threadIdx.x;
    int tx = tid & 15, ty = tid >> 4;
    size_t rowbase = (size_t)blockIdx.x * 128;

    float acc[8][8];
#pragma unroll
    for (int i = 0; i < 8; ++i)
#pragma unroll
        for (int jj = 0; jj < 8; ++jj) acc[i][jj] = 0.f;

    for (int k0 = 0; k0 < 128; k0 += 64) {
        __syncthreads();
        for (int idx = tid; idx < 128 * 64; idx += 256) {     // A: coalesced rows
            int r = idx >> 6, k = idx & 63;
            As[k * 132 + r] = X[(rowbase + r) * 128 + k0 + k];
        }
        for (int idx = tid; idx < 64 * 128; idx += 256) {     // B: W[k][c] direct
            int k = idx >> 7, c = idx & 127;
            Bs[k * 132 + c] = W[(size_t)(k0 + k) * 128 + c];
        }
        __syncthreads();
        GEMM_FRAG_LOOP(As, Bs)
    }

#pragma unroll
    for (int i = 0; i < 8; ++i) {
        int r = (i < 4) ? (ty * 4 + i) : (64 + ty * 4 + i - 4);
        float* crow = g_support + (rowbase + r) * 128;
        *(float4*)&crow[tx * 4]      = make_float4(acc[i][0], acc[i][1], acc[i][2], acc[i][3]);
        *(float4*)&crow[64 + tx * 4] = make_float4(acc[i][4], acc[i][5], acc[i][6], acc[i][7]);
    }
}

// ============================================================
// K2: edge scatter — one warp per edge, vectorized reduction.
// acc[s][dst] += vals[s][e] * support[s][src]
// ============================================================
__global__ void scatter_kernel(const int* __restrict__ adj_idx,
                               const float* __restrict__ adj_val) {
    int wid  = (int)((blockIdx.x * (size_t)blockDim.x + threadIdx.x) >> 5);
    int lane = threadIdx.x & 31;
    int s = wid >> 18;                 // E = 2^18
    int e = wid & (EE - 1);

    const int* ib = adj_idx + (size_t)s * 2 * EE;
    int dst = ib[e];
    int src = ib[EE + e];
    float v = adj_val[(size_t)s * EE + e];

    const float4* sp = (const float4*)(g_support + ((size_t)s * NN + src) * D);
    float* ap = g_acc + ((size_t)s * NN + dst) * D + lane * 4;
    float4 m = sp[lane];
    asm volatile("red.global.add.v4.f32 [%0], {%1, %2, %3, %4};"
                 :: "l"(ap), "f"(v * m.x), "f"(v * m.y), "f"(v * m.z), "f"(v * m.w)
                 : "memory");
}

// ============================================================
// K3: gates_x = relu(acc + gcn_bias) @ W_ih^T  (196608x512, K=128)
// grid (1536 row-blocks of 128, 4 col-blocks of 128)
// ============================================================
__global__ void __launch_bounds__(256)
gatesx_kernel(const float* __restrict__ wih, const float* __restrict__ gcn_bias) {
    extern __shared__ float sm[];
    float* As = sm;                 // [64][132]  As[k][r] = relu(acc+b)
    float* Bs = sm + 64 * 132;      // [64][132]  Bs[k][c] = wih[cb*128+c][k]

    int tid = threadIdx.x;
    int tx = tid & 15, ty = tid >> 4;
    size_t rowbase = (size_t)blockIdx.x * 128;
    int cb = blockIdx.y;

    float acc[8][8];
#pragma unroll
    for (int i = 0; i < 8; ++i)
#pragma unroll
        for (int jj = 0; jj < 8; ++jj) acc[i][jj] = 0.f;

    for (int k0 = 0; k0 < 128; k0 += 64) {
        __syncthreads();
        for (int idx = tid; idx < 128 * 64; idx += 256) {
            int r = idx >> 6, k = idx & 63;
            float x = g_acc[(rowbase + r) * 128 + k0 + k] + __ldg(&gcn_bias[k0 + k]);
            As[k * 132 + r] = fmaxf(x, 0.f);
        }
        for (int idx = tid; idx < 128 * 64; idx += 256) {     // idx = c*64 + k
            int c = idx >> 6, k = idx & 63;
            Bs[k * 132 + c] = wih[((size_t)(cb * 128 + c)) * 128 + k0 + k];
        }
        __syncthreads();
        GEMM_FRAG_LOOP(As, Bs)
    }

#pragma unroll
    for (int i = 0; i < 8; ++i) {
        int r = (i < 4) ? (ty * 4 + i) : (64 + ty * 4 + i - 4);
        float* crow = g_gx + (rowbase + r) * 512 + cb * 128;
        *(float4*)&crow[tx * 4]      = make_float4(acc[i][0], acc[i][1], acc[i][2], acc[i][3]);
        *(float4*)&crow[64 + tx * 4] = make_float4(acc[i][4], acc[i][5], acc[i][6], acc[i][7]);
    }
}

// ============================================================
// K4: LSTM recurrence — one CTA per batch lane, 512 threads.
// Thread j owns gate pre-activation j. W_hh: k in [0,32) via
// padded smem float4 loads, k in [32,128) register-resident.
// gx[t+1] prefetched (software pipeline). 4 accumulators.
// ============================================================
__device__ __forceinline__ float fsigm(float x) {
    return __fdividef(1.f, 1.f + __expf(-x));
}
__device__ __forceinline__ float ftanh(float x) {
    return __fdividef(2.f, 1.f + __expf(-2.f * x)) - 1.f;
}

__global__ void __launch_bounds__(512, 1)
lstm_kernel(const float* __restrict__ whh,
            const float* __restrict__ bih, const float* __restrict__ bhh,
            const float* __restrict__ h0,  const float* __restrict__ c0,
            float* __restrict__ out) {
    extern __shared__ float sm[];
    float* sW32 = sm;                 // [512][36]: sW32[j*36+k] = whh[j][k], k<32
    float* sH   = sm + 512 * 36;      // [128]
    float* sC   = sH + 128;           // [128]
    float* sG   = sC + 128;           // [512]

    int j = threadIdx.x;              // 0..511
    int b = blockIdx.x;               // 0..63

    // k in [0,32) -> smem (coalesced global reads)
    for (int idx = j; idx < 512 * 32; idx += 512) {
        int jj = idx >> 5, k = idx & 31;
        sW32[jj * 36 + k] = whh[(size_t)jj * 128 + k];
    }
    // k in [32,128) -> 96 registers
    float wreg[96];
#pragma unroll
    for (int k = 0; k < 96; ++k) wreg[k] = whh[(size_t)j * 128 + 32 + k];

    if (j < 128) {
        sH[j] = h0[b * 128 + j];
        sC[j] = c0[b * 128 + j];
    }
    float bias = bih[j] + bhh[j];
    __syncthreads();

    const float* gxp = g_gx + (size_t)b * 512 + j;
    float gx_cur = gxp[0];

    for (int t = 0; t < TT; ++t) {
        // prefetch next step's gx (hides DRAM latency behind this step)
        float gx_next = (t + 1 < TT) ? gxp[(size_t)(t + 1) * (64 * 512)] : 0.f;

        float a0 = 0.f, a1 = 0.f, a2 = 0.f, a3 = 0.f;
#pragma unroll
        for (int k = 0; k < 32; k += 4) {
            float4 w = *(const float4*)&sW32[j * 36 + k];
            float4 h = *(const float4*)&sH[k];
            a0 += h.x * w.x; a1 += h.y * w.y; a2 += h.z * w.z; a3 += h.w * w.w;
        }
#pragma unroll
        for (int k = 0; k < 96; k += 4) {
            float4 h = *(const float4*)&sH[32 + k];
            a0 += h.x * wreg[k + 0];
            a1 += h.y * wreg[k + 1];
            a2 += h.z * wreg[k + 2];
            a3 += h.w * wreg[k + 3];
        }
        sG[j] = ((a0 + a1) + (a2 + a3)) + gx_cur + bias;
        __syncthreads();

        if (j < 128) {
            float gi = sG[j], gf = sG[128 + j], gg = sG[256 + j], go = sG[384 + j];
            float c = fsigm(gf) * sC[j] + fsigm(gi) * ftanh(gg);
            sC[j] = c;
            float h = fsigm(go) * ftanh(c);
            sH[j] = h;
            out[((size_t)t * 64 + b) * 128 + j] = h;
        }
        __syncthreads();

        gx_cur = gx_next;
    }
}

// ============================================================
// launch
// ============================================================
extern "C" void kernel_launch(void* const* d_in, const int* in_sizes, int n_in,
                              void* d_out, int out_size) {
    const int*   adj_idx = (const int*)  d_in[0];
    const float* adj_val = (const float*)d_in[1];
    const float* xs      = (const float*)d_in[2];
    const float* gw      = (const float*)d_in[3];
    const float* gb      = (const float*)d_in[4];
    const float* wih     = (const float*)d_in[5];
    const float* whh     = (const float*)d_in[6];
    const float* bih     = (const float*)d_in[7];
    const float* bhh     = (const float*)d_in[8];
    const float* h0      = (const float*)d_in[9];
    const float* c0      = (const float*)d_in[10];
    float* out = (float*)d_out;

    (void)in_sizes; (void)n_in; (void)out_size;

    const int GEMM_SMEM = 2 * 64 * 132 * 4;                         // 67584
    const int LSTM_SMEM = (512 * 36 + 128 + 128 + 512) * 4;         // 76800

    static bool attr_done = false;
    if (!attr_done) {
        cudaFuncSetAttribute(support_kernel, cudaFuncAttributeMaxDynamicSharedMemorySize, GEMM_SMEM);
        cudaFuncSetAttribute(gatesx_kernel,  cudaFuncAttributeMaxDynamicSharedMemorySize, GEMM_SMEM);
        cudaFuncSetAttribute(lstm_kernel,    cudaFuncAttributeMaxDynamicSharedMemorySize, LSTM_SMEM);
        attr_done = true;
    }

    // zero acc: ROWS*D/4 float4 = 6,291,456 -> 24576 blocks
    zero_kernel<<<24576, 256>>>();

    // support GEMM: 196608/128 = 1536 blocks
    support_kernel<<<1536, 256, GEMM_SMEM>>>(xs, gw);

    // scatter: 12*262144 warps, 8 warps/block = 393216 blocks
    scatter_kernel<<<393216, 256>>>(adj_idx, adj_val);

    // gates_x GEMM: (1536 row-blocks, 4 col-blocks)
    gatesx_kernel<<<dim3(1536, 4), 256, GEMM_SMEM>>>(wih, gb);

    // recurrence: 64 independent chains, one CTA each
    lstm_kernel<<<64, 512, LSTM_SMEM>>>(whh, bih, bhh, h0, c0, out);
}

// round 5
// speedup vs baseline: 1.7794x; 1.0262x over previous
#include <cuda_runtime.h>
#include <cstdint>
#include <math.h>

#define S_T   12
#define NN    16384
#define EE    262144          // 2^18
#define D     128
#define BB    64
#define TT    3072            // S*N/B
#define ROWS  (S_T*NN)        // 196608
#define NEDGE (S_T*EE)        // 3,145,728

// ---- scratch (static device allocations; no runtime alloc allowed) ----
__device__ __align__(16) float g_support[(size_t)ROWS * D];     // ~100 MB
__device__ __align__(16) float g_acc[(size_t)ROWS * D];         // ~100 MB
__device__ __align__(16) float g_gx[(size_t)ROWS * 512];        // ~402 MB
__device__ int g_deg[ROWS];
__device__ int g_off[ROWS];
__device__ int g_cur[ROWS];
__device__ int g_bsum[256];
__device__ int g_eidx[NEDGE];

// ---- packed f32x2 helpers ----
__device__ __forceinline__ void ffma2(unsigned long long& d, unsigned long long a,
                                      unsigned long long b, unsigned long long c) {
    asm("fma.rn.f32x2 %0, %1, %2, %3;" : "=l"(d) : "l"(a), "l"(b), "l"(c));
}
__device__ __forceinline__ unsigned long long bcast2(float x) {
    unsigned long long r;
    asm("mov.b64 %0, {%1, %1};" : "=l"(r) : "f"(x));
    return r;
}
__device__ __forceinline__ float2 unpack2(unsigned long long v) {
    float2 r;
    asm("mov.b64 {%0, %1}, %2;" : "=f"(r.x), "=f"(r.y) : "l"(v));
    return r;
}

// ============================================================
// CSR pipeline: histogram -> scan -> fill
// ============================================================
__global__ void zero_deg_kernel() {
    int gid = blockIdx.x * 1024 + threadIdx.x;
    g_deg[gid] = 0;
}

__global__ void hist_kernel(const int* __restrict__ adj_idx) {
    int gid = blockIdx.x * 1024 + threadIdx.x;   // 0..NEDGE-1
    int s = gid >> 18, e = gid & (EE - 1);
    int dst = adj_idx[(size_t)s * 2 * EE + e];
    atomicAdd(&g_deg[s * NN + dst], 1);
}

__global__ void scan1_kernel() {                 // 192 blocks x 1024
    __shared__ int tmp[1024];
    int tid = threadIdx.x;
    int gid = blockIdx.x * 1024 + tid;
    int x = g_deg[gid];
    tmp[tid] = x;
    __syncthreads();
#pragma unroll
    for (int d = 1; d < 1024; d <<= 1) {
        int t = (tid >= d) ? tmp[tid - d] : 0;
        __syncthreads();
        tmp[tid] += t;
        __syncthreads();
    }
    g_off[gid] = tmp[tid] - x;                   // exclusive
    if (tid == 1023) g_bsum[blockIdx.x] = tmp[tid];
}

__global__ void scan2_kernel() {                 // 1 block x 256
    __shared__ int tmp[256];
    int tid = threadIdx.x;
    int x = (tid < 192) ? g_bsum[tid] : 0;
    tmp[tid] = x;
    __syncthreads();
#pragma unroll
    for (int d = 1; d < 256; d <<= 1) {
        int t = (tid >= d) ? tmp[tid - d] : 0;
        __syncthreads();
        tmp[tid] += t;
        __syncthreads();
    }
    if (tid < 192) g_bsum[tid] = tmp[tid] - x;   // exclusive
}

__global__ void scan3_kernel() {                 // 192 blocks x 1024
    int gid = blockIdx.x * 1024 + threadIdx.x;
    int v = g_off[gid] + g_bsum[blockIdx.x];
    g_off[gid] = v;
    g_cur[gid] = v;
}

__global__ void fill_kernel(const int* __restrict__ adj_idx) {
    int gid = blockIdx.x * 1024 + threadIdx.x;
    int s = gid >> 18, e = gid & (EE - 1);
    int dst = adj_idx[(size_t)s * 2 * EE + e];
    int pos = atomicAdd(&g_cur[s * NN + dst], 1);
    g_eidx[pos] = e;
}

// ============================================================
// gather: acc[row] = sum_e val[e] * support[src[e]]
// one warp per row; lane owns 4 consecutive columns.
// ============================================================
__global__ void __launch_bounds__(256)
gather_kernel(const int* __restrict__ adj_idx, const float* __restrict__ adj_val) {
    int wid  = blockIdx.x * 8 + (threadIdx.x >> 5);   // row id
    int lane = threadIdx.x & 31;
    int s = wid >> 14;                                // NN = 2^14

    int start = g_off[wid];
    int cnt   = g_deg[wid];

    const int*   srcs = adj_idx + (size_t)s * 2 * EE + EE;
    const float* vals = adj_val + (size_t)s * EE;
    const float* supp = g_support + (size_t)s * NN * D + lane * 4;

    float ax = 0.f, ay = 0.f, az = 0.f, aw = 0.f;
#pragma unroll 2
    for (int i = 0; i < cnt; ++i) {
        int e = __ldg(&g_eidx[start + i]);
        int src = __ldg(&srcs[e]);
        float v = __ldg(&vals[e]);
        float4 m = *(const float4*)(supp + (size_t)src * D);
        ax += v * m.x; ay += v * m.y; az += v * m.z; aw += v * m.w;
    }
    *(float4*)(g_acc + (size_t)wid * D + lane * 4) = make_float4(ax, ay, az, aw);
}

// ============================================================
// Register-tiled fp32 GEMM core: 128x128 block, 256 threads,
// 8x8 per thread, packed f32x2 FMAs.
// ============================================================
typedef unsigned long long u64;

#define GEMM_FRAG_LOOP(As, Bs)                                              \
    _Pragma("unroll")                                                       \
    for (int k = 0; k < 64; ++k) {                                          \
        ulonglong2 b0 = *(const ulonglong2*)&Bs[k * 132 + tx * 4];          \
        ulonglong2 b1 = *(const ulonglong2*)&Bs[k * 132 + 64 + tx * 4];     \
        float4 a0 = *(const float4*)&As[k * 132 + ty * 4];                  \
        float4 a1 = *(const float4*)&As[k * 132 + 64 + ty * 4];             \
        float af[8] = {a0.x,a0.y,a0.z,a0.w,a1.x,a1.y,a1.z,a1.w};            \
        _Pragma("unroll")                                                   \
        for (int i = 0; i < 8; ++i) {                                       \
            u64 ap = bcast2(af[i]);                                         \
            ffma2(accp[i][0], ap, b0.x, accp[i][0]);                        \
            ffma2(accp[i][1], ap, b0.y, accp[i][1]);                        \
            ffma2(accp[i][2], ap, b1.x, accp[i][2]);                        \
            ffma2(accp[i][3], ap, b1.y, accp[i][3]);                        \
        }                                                                   \
    }

#define GEMM_STORE(dstbase, ldc)                                            \
    _Pragma("unroll")                                                       \
    for (int i = 0; i < 8; ++i) {                                           \
        int r = (i < 4) ? (ty * 4 + i) : (64 + ty * 4 + i - 4);             \
        float* crow = (dstbase) + (size_t)r * (ldc);                        \
        float2 v0 = unpack2(accp[i][0]), v1 = unpack2(accp[i][1]);          \
        float2 v2 = unpack2(accp[i][2]), v3 = unpack2(accp[i][3]);          \
        *(float4*)&crow[tx * 4]      = make_float4(v0.x, v0.y, v1.x, v1.y); \
        *(float4*)&crow[64 + tx * 4] = make_float4(v2.x, v2.y, v3.x, v3.y); \
    }

// ============================================================
// K1: support = xs @ gcn_weight   (196608x128 @ 128x128)
// ============================================================
__global__ void __launch_bounds__(256)
support_kernel(const float* __restrict__ X, const float* __restrict__ W) {
    extern __shared__ float sm[];
    float* As = sm;                 // [64][132]  (As[k][r])
    float* Bs = sm + 64 * 132;      // [64][132]  (Bs[k][c])

    int tid = threadIdx.x;
    int tx = tid & 15, ty = tid >> 4;
    size_t rowbase = (size_t)blockIdx.x * 128;

    u64 accp[8][4];
#pragma unroll
    for (int i = 0; i < 8; ++i)
#pragma unroll
        for (int jj = 0; jj < 4; ++jj) accp[i][jj] = 0ull;

    for (int k0 = 0; k0 < 128; k0 += 64) {
        __syncthreads();
        for (int idx = tid; idx < 128 * 64; idx += 256) {     // A
            int r = idx >> 6, k = idx & 63;
            As[k * 132 + r] = X[(rowbase + r) * 128 + k0 + k];
        }
        for (int idx = tid; idx < 64 * 128; idx += 256) {     // B: W[k][c]
            int k = idx >> 7, c = idx & 127;
            Bs[k * 132 + c] = W[(size_t)(k0 + k) * 128 + c];
        }
        __syncthreads();
        GEMM_FRAG_LOOP(As, Bs)
    }
    float* base = g_support + rowbase * 128;
    GEMM_STORE(base, 128)
}

// ============================================================
// K3: gates_x = relu(acc + gcn_bias) @ W_ih^T  (196608x512, K=128)
// ============================================================
__global__ void __launch_bounds__(256)
gatesx_kernel(const float* __restrict__ wih, const float* __restrict__ gcn_bias) {
    extern __shared__ float sm[];
    float* As = sm;                 // [64][132]  As[k][r] = relu(acc+b)
    float* Bs = sm + 64 * 132;      // [64][132]  Bs[k][c] = wih[cb*128+c][k]

    int tid = threadIdx.x;
    int tx = tid & 15, ty = tid >> 4;
    size_t rowbase = (size_t)blockIdx.x * 128;
    int cb = blockIdx.y;

    u64 accp[8][4];
#pragma unroll
    for (int i = 0; i < 8; ++i)
#pragma unroll
        for (int jj = 0; jj < 4; ++jj) accp[i][jj] = 0ull;

    for (int k0 = 0; k0 < 128; k0 += 64) {
        __syncthreads();
        for (int idx = tid; idx < 128 * 64; idx += 256) {
            int r = idx >> 6, k = idx & 63;
            float x = g_acc[(rowbase + r) * 128 + k0 + k] + __ldg(&gcn_bias[k0 + k]);
            As[k * 132 + r] = fmaxf(x, 0.f);
        }
        for (int idx = tid; idx < 128 * 64; idx += 256) {     // idx = c*64 + k
            int c = idx >> 6, k = idx & 63;
            Bs[k * 132 + c] = wih[((size_t)(cb * 128 + c)) * 128 + k0 + k];
        }
        __syncthreads();
        GEMM_FRAG_LOOP(As, Bs)
    }
    float* base = g_gx + rowbase * 512 + cb * 128;
    GEMM_STORE(base, 512)
}

// ============================================================
// K4: LSTM recurrence — one CTA per batch lane, 512 threads.
// W_hh: k in [0,32) smem (padded), k in [32,128) registers,
// packed f32x2 FMAs. gx[t+1] prefetched.
// ============================================================
__device__ __forceinline__ float fsigm(float x) {
    return __fdividef(1.f, 1.f + __expf(-x));
}
__device__ __forceinline__ float ftanh(float x) {
    return __fdividef(2.f, 1.f + __expf(-2.f * x)) - 1.f;
}

__global__ void __launch_bounds__(512, 1)
lstm_kernel(const float* __restrict__ whh,
            const float* __restrict__ bih, const float* __restrict__ bhh,
            const float* __restrict__ h0,  const float* __restrict__ c0,
            float* __restrict__ out) {
    extern __shared__ float sm[];
    float* sW32 = sm;                 // [512][36]: sW32[j*36+k] = whh[j][k], k<32
    float* sH   = sm + 512 * 36;      // [128]
    float* sC   = sH + 128;           // [128]
    float* sG   = sC + 128;           // [512]

    int j = threadIdx.x;              // 0..511
    int b = blockIdx.x;               // 0..63

    for (int idx = j; idx < 512 * 32; idx += 512) {
        int jj = idx >> 5, k = idx & 31;
        sW32[jj * 36 + k] = whh[(size_t)jj * 128 + k];
    }
    u64 wreg2[48];                    // k in [32,128), packed pairs
#pragma unroll
    for (int k = 0; k < 48; ++k)
        wreg2[k] = *(const u64*)&whh[(size_t)j * 128 + 32 + 2 * k];

    if (j < 128) {
        sH[j] = h0[b * 128 + j];
        sC[j] = c0[b * 128 + j];
    }
    float bias = bih[j] + bhh[j];
    __syncthreads();

    const float* gxp = g_gx + (size_t)b * 512 + j;
    float gx_cur = gxp[0];

    for (int t = 0; t < TT; ++t) {
        float gx_next = (t + 1 < TT) ? gxp[(size_t)(t + 1) * (64 * 512)] : 0.f;

        u64 acc01 = 0ull, acc23 = 0ull;
#pragma unroll
        for (int k = 0; k < 32; k += 4) {
            ulonglong2 w = *(const ulonglong2*)&sW32[j * 36 + k];
            ulonglong2 h = *(const ulonglong2*)&sH[k];
            ffma2(acc01, h.x, w.x, acc01);
            ffma2(acc23, h.y, w.y, acc23);
        }
#pragma unroll
        for (int k = 0; k < 96; k += 4) {
            ulonglong2 h = *(const ulonglong2*)&sH[32 + k];
            ffma2(acc01, h.x, wreg2[k / 2], acc01);
            ffma2(acc23, h.y, wreg2[k / 2 + 1], acc23);
        }
        float2 p01 = unpack2(acc01), p23 = unpack2(acc23);
        sG[j] = ((p01.x + p01.y) + (p23.x + p23.y)) + gx_cur + bias;
        __syncthreads();

        if (j < 128) {
            float gi = sG[j], gf = sG[128 + j], gg = sG[256 + j], go = sG[384 + j];
            float c = fsigm(gf) * sC[j] + fsigm(gi) * ftanh(gg);
            sC[j] = c;
            float h = fsigm(go) * ftanh(c);
            sH[j] = h;
            out[((size_t)t * 64 + b) * 128 + j] = h;
        }
        __syncthreads();

        gx_cur = gx_next;
    }
}

// ============================================================
// launch
// ============================================================
extern "C" void kernel_launch(void* const* d_in, const int* in_sizes, int n_in,
                              void* d_out, int out_size) {
    const int*   adj_idx = (const int*)  d_in[0];
    const float* adj_val = (const float*)d_in[1];
    const float* xs      = (const float*)d_in[2];
    const float* gw      = (const float*)d_in[3];
    const float* gb      = (const float*)d_in[4];
    const float* wih     = (const float*)d_in[5];
    const float* whh     = (const float*)d_in[6];
    const float* bih     = (const float*)d_in[7];
    const float* bhh     = (const float*)d_in[8];
    const float* h0      = (const float*)d_in[9];
    const float* c0      = (const float*)d_in[10];
    float* out = (float*)d_out;

    (void)in_sizes; (void)n_in; (void)out_size;

    const int GEMM_SMEM = 2 * 64 * 132 * 4;                         // 67584
    const int LSTM_SMEM = (512 * 36 + 128 + 128 + 512) * 4;         // 76800

    static bool attr_done = false;
    if (!attr_done) {
        cudaFuncSetAttribute(support_kernel, cudaFuncAttributeMaxDynamicSharedMemorySize, GEMM_SMEM);
        cudaFuncSetAttribute(gatesx_kernel,  cudaFuncAttributeMaxDynamicSharedMemorySize, GEMM_SMEM);
        cudaFuncSetAttribute(lstm_kernel,    cudaFuncAttributeMaxDynamicSharedMemorySize, LSTM_SMEM);
        attr_done = true;
    }

    // CSR build
    zero_deg_kernel<<<192, 1024>>>();
    hist_kernel<<<NEDGE / 1024, 1024>>>(adj_idx);
    scan1_kernel<<<192, 1024>>>();
    scan2_kernel<<<1, 256>>>();
    scan3_kernel<<<192, 1024>>>();
    fill_kernel<<<NEDGE / 1024, 1024>>>(adj_idx);

    // support GEMM: 196608/128 = 1536 blocks
    support_kernel<<<1536, 256, GEMM_SMEM>>>(xs, gw);

    // gather: 196608 warps, 8/block
    gather_kernel<<<ROWS / 8, 256>>>(adj_idx, adj_val);

    // gates_x GEMM: (1536 row-blocks, 4 col-blocks)
    gatesx_kernel<<<dim3(1536, 4), 256, GEMM_SMEM>>>(wih, gb);

    // recurrence: 64 independent chains, one CTA each
    lstm_kernel<<<64, 512, LSTM_SMEM>>>(whh, bih, bhh, h0, c0, out);
}

// round 6
// speedup vs baseline: 1.7841x; 1.0026x over previous
#include <cuda_runtime.h>
#include <cstdint>
#include <math.h>

#define S_T   12
#define NN    16384
#define EE    262144          // 2^18
#define D     128
#define BB    64
#define TT    3072            // S*N/B
#define ROWS  (S_T*NN)        // 196608
#define NEDGE (S_T*EE)        // 3,145,728

// ---- scratch (static device allocations; no runtime alloc allowed) ----
__device__ __align__(16) float g_support[(size_t)ROWS * D];     // ~100 MB
__device__ __align__(16) float g_acc[(size_t)ROWS * D];         // ~100 MB
__device__ __align__(16) float g_gx[(size_t)ROWS * 512];        // ~402 MB
__device__ int g_deg[ROWS];
__device__ int g_off[ROWS];
__device__ int g_cur[ROWS];
__device__ int g_bsum[256];
__device__ __align__(16) int2 g_epack[NEDGE];                   // (src, val_bits) per edge, CSR order

// ---- packed f32x2 helpers ----
__device__ __forceinline__ void ffma2(unsigned long long& d, unsigned long long a,
                                      unsigned long long b, unsigned long long c) {
    asm("fma.rn.f32x2 %0, %1, %2, %3;" : "=l"(d) : "l"(a), "l"(b), "l"(c));
}
__device__ __forceinline__ unsigned long long bcast2(float x) {
    unsigned long long r;
    asm("mov.b64 %0, {%1, %1};" : "=l"(r) : "f"(x));
    return r;
}
__device__ __forceinline__ float2 unpack2(unsigned long long v) {
    float2 r;
    asm("mov.b64 {%0, %1}, %2;" : "=f"(r.x), "=f"(r.y) : "l"(v));
    return r;
}

// ============================================================
// CSR pipeline: histogram -> scan -> fill (packs src+val)
// ============================================================
__global__ void zero_deg_kernel() {
    int gid = blockIdx.x * 1024 + threadIdx.x;
    g_deg[gid] = 0;
}

__global__ void hist_kernel(const int* __restrict__ adj_idx) {
    int gid = blockIdx.x * 1024 + threadIdx.x;   // 0..NEDGE-1
    int s = gid >> 18, e = gid & (EE - 1);
    int dst = adj_idx[(size_t)s * 2 * EE + e];
    atomicAdd(&g_deg[s * NN + dst], 1);
}

__global__ void scan1_kernel() {                 // 192 blocks x 1024
    __shared__ int tmp[1024];
    int tid = threadIdx.x;
    int gid = blockIdx.x * 1024 + tid;
    int x = g_deg[gid];
    tmp[tid] = x;
    __syncthreads();
#pragma unroll
    for (int d = 1; d < 1024; d <<= 1) {
        int t = (tid >= d) ? tmp[tid - d] : 0;
        __syncthreads();
        tmp[tid] += t;
        __syncthreads();
    }
    g_off[gid] = tmp[tid] - x;                   // exclusive
    if (tid == 1023) g_bsum[blockIdx.x] = tmp[tid];
}

__global__ void scan2_kernel() {                 // 1 block x 256
    __shared__ int tmp[256];
    int tid = threadIdx.x;
    int x = (tid < 192) ? g_bsum[tid] : 0;
    tmp[tid] = x;
    __syncthreads();
#pragma unroll
    for (int d = 1; d < 256; d <<= 1) {
        int t = (tid >= d) ? tmp[tid - d] : 0;
        __syncthreads();
        tmp[tid] += t;
        __syncthreads();
    }
    if (tid < 192) g_bsum[tid] = tmp[tid] - x;   // exclusive
}

__global__ void scan3_kernel() {                 // 192 blocks x 1024
    int gid = blockIdx.x * 1024 + threadIdx.x;
    int v = g_off[gid] + g_bsum[blockIdx.x];
    g_off[gid] = v;
    g_cur[gid] = v;
}

__global__ void fill_kernel(const int* __restrict__ adj_idx,
                            const float* __restrict__ adj_val) {
    int gid = blockIdx.x * 1024 + threadIdx.x;
    int s = gid >> 18, e = gid & (EE - 1);
    const int* ib = adj_idx + (size_t)s * 2 * EE;
    int dst = ib[e];                              // coalesced
    int src = ib[EE + e];                         // coalesced
    float v  = adj_val[(size_t)s * EE + e];       // coalesced
    int pos = atomicAdd(&g_cur[s * NN + dst], 1);
    g_epack[pos] = make_int2(src, __float_as_int(v));
}

// ============================================================
// gather: acc[row] = sum_e val[e] * support[src[e]]
// one warp per row; lane owns 4 consecutive columns.
// Edge stream is packed (src,val) -> 1 uniform 8B load +
// 1 coalesced 512B row load per edge; 4 rows in flight.
// ============================================================
__global__ void __launch_bounds__(256)
gather_kernel() {
    int wid  = blockIdx.x * 8 + (threadIdx.x >> 5);   // row id
    int lane = threadIdx.x & 31;
    int s = wid >> 14;                                // NN = 2^14

    int start = g_off[wid];
    int cnt   = g_deg[wid];

    const int2*  epk  = g_epack + start;
    const float* supp = g_support + (size_t)s * NN * D + lane * 4;

    float ax = 0.f, ay = 0.f, az = 0.f, aw = 0.f;
    int i = 0;
    for (; i + 4 <= cnt; i += 4) {
        int2 p0 = __ldg(&epk[i + 0]);
        int2 p1 = __ldg(&epk[i + 1]);
        int2 p2 = __ldg(&epk[i + 2]);
        int2 p3 = __ldg(&epk[i + 3]);
        float4 m0 = *(const float4*)(supp + (size_t)p0.x * D);
        float4 m1 = *(const float4*)(supp + (size_t)p1.x * D);
        float4 m2 = *(const float4*)(supp + (size_t)p2.x * D);
        float4 m3 = *(const float4*)(supp + (size_t)p3.x * D);
        float v0 = __int_as_float(p0.y), v1 = __int_as_float(p1.y);
        float v2 = __int_as_float(p2.y), v3 = __int_as_float(p3.y);
        ax += v0 * m0.x; ay += v0 * m0.y; az += v0 * m0.z; aw += v0 * m0.w;
        ax += v1 * m1.x; ay += v1 * m1.y; az += v1 * m1.z; aw += v1 * m1.w;
        ax += v2 * m2.x; ay += v2 * m2.y; az += v2 * m2.z; aw += v2 * m2.w;
        ax += v3 * m3.x; ay += v3 * m3.y; az += v3 * m3.z; aw += v3 * m3.w;
    }
    for (; i < cnt; ++i) {
        int2 p = __ldg(&epk[i]);
        float v = __int_as_float(p.y);
        float4 m = *(const float4*)(supp + (size_t)p.x * D);
        ax += v * m.x; ay += v * m.y; az += v * m.z; aw += v * m.w;
    }
    *(float4*)(g_acc + (size_t)wid * D + lane * 4) = make_float4(ax, ay, az, aw);
}

// ============================================================
// Register-tiled fp32 GEMM core: 128x128 block, 256 threads,
// 8x8 per thread, packed f32x2 FMAs.
// ============================================================
typedef unsigned long long u64;

#define GEMM_FRAG_LOOP(As, Bs)                                              \
    _Pragma("unroll")                                                       \
    for (int k = 0; k < 64; ++k) {                                          \
        ulonglong2 b0 = *(const ulonglong2*)&Bs[k * 132 + tx * 4];          \
        ulonglong2 b1 = *(const ulonglong2*)&Bs[k * 132 + 64 + tx * 4];     \
        float4 a0 = *(const float4*)&As[k * 132 + ty * 4];                  \
        float4 a1 = *(const float4*)&As[k * 132 + 64 + ty * 4];             \
        float af[8] = {a0.x,a0.y,a0.z,a0.w,a1.x,a1.y,a1.z,a1.w};            \
        _Pragma("unroll")                                                   \
        for (int i = 0; i < 8; ++i) {                                       \
            u64 ap = bcast2(af[i]);                                         \
            ffma2(accp[i][0], ap, b0.x, accp[i][0]);                        \
            ffma2(accp[i][1], ap, b0.y, accp[i][1]);                        \
            ffma2(accp[i][2], ap, b1.x, accp[i][2]);                        \
            ffma2(accp[i][3], ap, b1.y, accp[i][3]);                        \
        }                                                                   \
    }

#define GEMM_STORE(dstbase, ldc)                                            \
    _Pragma("unroll")                                                       \
    for (int i = 0; i < 8; ++i) {                                           \
        int r = (i < 4) ? (ty * 4 + i) : (64 + ty * 4 + i - 4);             \
        float* crow = (dstbase) + (size_t)r * (ldc);                        \
        float2 v0 = unpack2(accp[i][0]), v1 = unpack2(accp[i][1]);          \
        float2 v2 = unpack2(accp[i][2]), v3 = unpack2(accp[i][3]);          \
        *(float4*)&crow[tx * 4]      = make_float4(v0.x, v0.y, v1.x, v1.y); \
        *(float4*)&crow[64 + tx * 4] = make_float4(v2.x, v2.y, v3.x, v3.y); \
    }

// ============================================================
// K1: support = xs @ gcn_weight   (196608x128 @ 128x128)
// ============================================================
__global__ void __launch_bounds__(256)
support_kernel(const float* __restrict__ X, const float* __restrict__ W) {
    extern __shared__ float sm[];
    float* As = sm;                 // [64][132]  (As[k][r])
    float* Bs = sm + 64 * 132;      // [64][132]  (Bs[k][c])

    int tid = threadIdx.x;
    int tx = tid & 15, ty = tid >> 4;
    size_t rowbase = (size_t)blockIdx.x * 128;

    u64 accp[8][4];
#pragma unroll
    for (int i = 0; i < 8; ++i)
#pragma unroll
        for (int jj = 0; jj < 4; ++jj) accp[i][jj] = 0ull;

    for (int k0 = 0; k0 < 128; k0 += 64) {
        __syncthreads();
        for (int idx = tid; idx < 128 * 64; idx += 256) {     // A
            int r = idx >> 6, k = idx & 63;
            As[k * 132 + r] = X[(rowbase + r) * 128 + k0 + k];
        }
        for (int idx = tid; idx < 64 * 128; idx += 256) {     // B: W[k][c]
            int k = idx >> 7, c = idx & 127;
            Bs[k * 132 + c] = W[(size_t)(k0 + k) * 128 + c];
        }
        __syncthreads();
        GEMM_FRAG_LOOP(As, Bs)
    }
    float* base = g_support + rowbase * 128;
    GEMM_STORE(base, 128)
}

// ============================================================
// K3: gates_x = relu(acc + gcn_bias) @ W_ih^T  (196608x512, K=128)
// ============================================================
__global__ void __launch_bounds__(256)
gatesx_kernel(const float* __restrict__ wih, const float* __restrict__ gcn_bias) {
    extern __shared__ float sm[];
    float* As = sm;                 // [64][132]  As[k][r] = relu(acc+b)
    float* Bs = sm + 64 * 132;      // [64][132]  Bs[k][c] = wih[cb*128+c][k]

    int tid = threadIdx.x;
    int tx = tid & 15, ty = tid >> 4;
    size_t rowbase = (size_t)blockIdx.x * 128;
    int cb = blockIdx.y;

    u64 accp[8][4];
#pragma unroll
    for (int i = 0; i < 8; ++i)
#pragma unroll
        for (int jj = 0; jj < 4; ++jj) accp[i][jj] = 0ull;

    for (int k0 = 0; k0 < 128; k0 += 64) {
        __syncthreads();
        for (int idx = tid; idx < 128 * 64; idx += 256) {
            int r = idx >> 6, k = idx & 63;
            float x = g_acc[(rowbase + r) * 128 + k0 + k] + __ldg(&gcn_bias[k0 + k]);
            As[k * 132 + r] = fmaxf(x, 0.f);
        }
        for (int idx = tid; idx < 128 * 64; idx += 256) {     // idx = c*64 + k
            int c = idx >> 6, k = idx & 63;
            Bs[k * 132 + c] = wih[((size_t)(cb * 128 + c)) * 128 + k0 + k];
        }
        __syncthreads();
        GEMM_FRAG_LOOP(As, Bs)
    }
    float* base = g_gx + rowbase * 512 + cb * 128;
    GEMM_STORE(base, 512)
}

// ============================================================
// K4: LSTM recurrence — one CTA per batch lane, 512 threads.
// W_hh: k in [0,32) smem (padded), k in [32,128) registers,
// packed f32x2 FMAs. gx[t+1] prefetched.
// ============================================================
__device__ __forceinline__ float fsigm(float x) {
    return __fdividef(1.f, 1.f + __expf(-x));
}
__device__ __forceinline__ float ftanh(float x) {
    return __fdividef(2.f, 1.f + __expf(-2.f * x)) - 1.f;
}

__global__ void __launch_bounds__(512, 1)
lstm_kernel(const float* __restrict__ whh,
            const float* __restrict__ bih, const float* __restrict__ bhh,
            const float* __restrict__ h0,  const float* __restrict__ c0,
            float* __restrict__ out) {
    extern __shared__ float sm[];
    float* sW32 = sm;                 // [512][36]: sW32[j*36+k] = whh[j][k], k<32
    float* sH   = sm + 512 * 36;      // [128]
    float* sC   = sH + 128;           // [128]
    float* sG   = sC + 128;           // [512]

    int j = threadIdx.x;              // 0..511
    int b = blockIdx.x;               // 0..63

    for (int idx = j; idx < 512 * 32; idx += 512) {
        int jj = idx >> 5, k = idx & 31;
        sW32[jj * 36 + k] = whh[(size_t)jj * 128 + k];
    }
    u64 wreg2[48];                    // k in [32,128), packed pairs
#pragma unroll
    for (int k = 0; k < 48; ++k)
        wreg2[k] = *(const u64*)&whh[(size_t)j * 128 + 32 + 2 * k];

    if (j < 128) {
        sH[j] = h0[b * 128 + j];
        sC[j] = c0[b * 128 + j];
    }
    float bias = bih[j] + bhh[j];
    __syncthreads();

    const float* gxp = g_gx + (size_t)b * 512 + j;
    float gx_cur = gxp[0];

    for (int t = 0; t < TT; ++t) {
        float gx_next = (t + 1 < TT) ? gxp[(size_t)(t + 1) * (64 * 512)] : 0.f;

        u64 acc01 = 0ull, acc23 = 0ull;
#pragma unroll
        for (int k = 0; k < 32; k += 4) {
            ulonglong2 w = *(const ulonglong2*)&sW32[j * 36 + k];
            ulonglong2 h = *(const ulonglong2*)&sH[k];
            ffma2(acc01, h.x, w.x, acc01);
            ffma2(acc23, h.y, w.y, acc23);
        }
#pragma unroll
        for (int k = 0; k < 96; k += 4) {
            ulonglong2 h = *(const ulonglong2*)&sH[32 + k];
            ffma2(acc01, h.x, wreg2[k / 2], acc01);
            ffma2(acc23, h.y, wreg2[k / 2 + 1], acc23);
        }
        float2 p01 = unpack2(acc01), p23 = unpack2(acc23);
        sG[j] = ((p01.x + p01.y) + (p23.x + p23.y)) + gx_cur + bias;
        __syncthreads();

        if (j < 128) {
            float gi = sG[j], gf = sG[128 + j], gg = sG[256 + j], go = sG[384 + j];
            float c = fsigm(gf) * sC[j] + fsigm(gi) * ftanh(gg);
            sC[j] = c;
            float h = fsigm(go) * ftanh(c);
            sH[j] = h;
            out[((size_t)t * 64 + b) * 128 + j] = h;
        }
        __syncthreads();

        gx_cur = gx_next;
    }
}

// ============================================================
// launch
// ============================================================
extern "C" void kernel_launch(void* const* d_in, const int* in_sizes, int n_in,
                              void* d_out, int out_size) {
    const int*   adj_idx = (const int*)  d_in[0];
    const float* adj_val = (const float*)d_in[1];
    const float* xs      = (const float*)d_in[2];
    const float* gw      = (const float*)d_in[3];
    const float* gb      = (const float*)d_in[4];
    const float* wih     = (const float*)d_in[5];
    const float* whh     = (const float*)d_in[6];
    const float* bih     = (const float*)d_in[7];
    const float* bhh     = (const float*)d_in[8];
    const float* h0      = (const float*)d_in[9];
    const float* c0      = (const float*)d_in[10];
    float* out = (float*)d_out;

    (void)in_sizes; (void)n_in; (void)out_size;

    const int GEMM_SMEM = 2 * 64 * 132 * 4;                         // 67584
    const int LSTM_SMEM = (512 * 36 + 128 + 128 + 512) * 4;         // 76800

    static bool attr_done = false;
    if (!attr_done) {
        cudaFuncSetAttribute(support_kernel, cudaFuncAttributeMaxDynamicSharedMemorySize, GEMM_SMEM);
        cudaFuncSetAttribute(gatesx_kernel,  cudaFuncAttributeMaxDynamicSharedMemorySize, GEMM_SMEM);
        cudaFuncSetAttribute(lstm_kernel,    cudaFuncAttributeMaxDynamicSharedMemorySize, LSTM_SMEM);
        attr_done = true;
    }

    // CSR build (packs (src,val) per destination row)
    zero_deg_kernel<<<192, 1024>>>();
    hist_kernel<<<NEDGE / 1024, 1024>>>(adj_idx);
    scan1_kernel<<<192, 1024>>>();
    scan2_kernel<<<1, 256>>>();
    scan3_kernel<<<192, 1024>>>();
    fill_kernel<<<NEDGE / 1024, 1024>>>(adj_idx, adj_val);

    // support GEMM: 196608/128 = 1536 blocks
    support_kernel<<<1536, 256, GEMM_SMEM>>>(xs, gw);

    // gather: 196608 warps, 8/block
    gather_kernel<<<ROWS / 8, 256>>>();

    // gates_x GEMM: (1536 row-blocks, 4 col-blocks)
    gatesx_kernel<<<dim3(1536, 4), 256, GEMM_SMEM>>>(wih, gb);

    // recurrence: 64 independent chains, one CTA each
    lstm_kernel<<<64, 512, LSTM_SMEM>>>(whh, bih, bhh, h0, c0, out);
}

// round 9
// speedup vs baseline: 2.2150x; 1.2415x over previous
#include <cuda_runtime.h>
#include <cstdint>
#include <math.h>

#define S_T   12
#define NN    16384
#define EE    262144          // 2^18
#define D     128
#define BB    64
#define TT    3072            // S*N/B
#define ROWS  (S_T*NN)        // 196608
#define NEDGE (S_T*EE)        // 3,145,728
#define NRB   1536            // row-blocks of 128 rows (= 2 timesteps each)
#define TSPLIT 1024           // LSTM split point (timesteps)
#define ITEM_OFS 2048         // first gatesx item handled inside combo (= rb 512)
#define NITEMS_TOT (NRB*4)    // 6144

// ---- scratch (static device allocations; no runtime alloc allowed) ----
__device__ __align__(16) float g_support[(size_t)ROWS * D];     // ~100 MB
__device__ __align__(16) float g_acc[(size_t)ROWS * D];         // ~100 MB
__device__ __align__(16) float g_gx[(size_t)ROWS * 512];        // ~402 MB
__device__ int g_deg[ROWS];
__device__ int g_off[ROWS];
__device__ int g_cur[ROWS];
__device__ int g_bsum[256];
__device__ __align__(16) int2 g_epack[NEDGE];                   // (src, val_bits), CSR order
__device__ int g_ticket;
__device__ __align__(16) float g_hstate[BB * 128];
__device__ __align__(16) float g_cstate[BB * 128];

// ---- packed f32x2 helpers ----
typedef unsigned long long u64;
__device__ __forceinline__ void ffma2(u64& d, u64 a, u64 b, u64 c) {
    asm("fma.rn.f32x2 %0, %1, %2, %3;" : "=l"(d) : "l"(a), "l"(b), "l"(c));
}
__device__ __forceinline__ u64 bcast2(float x) {
    u64 r;
    asm("mov.b64 %0, {%1, %1};" : "=l"(r) : "f"(x));
    return r;
}
__device__ __forceinline__ float2 unpack2(u64 v) {
    float2 r;
    asm("mov.b64 {%0, %1}, %2;" : "=f"(r.x), "=f"(r.y) : "l"(v));
    return r;
}
__device__ __forceinline__ float fsigm(float x) {
    return __fdividef(1.f, 1.f + __expf(-x));
}
__device__ __forceinline__ float ftanh(float x) {
    return __fdividef(2.f, 1.f + __expf(-2.f * x)) - 1.f;
}

// ============================================================
// init: zero degree counters + ticket
// ============================================================
__global__ void init_kernel() {
    int gid = blockIdx.x * 1024 + threadIdx.x;
    g_deg[gid] = 0;
    if (gid == 0) g_ticket = 0;
}

// ============================================================
// CSR pipeline: histogram -> scan -> fill (packs src+val)
// ============================================================
__global__ void hist_kernel(const int* __restrict__ adj_idx) {
    int gid = blockIdx.x * 1024 + threadIdx.x;   // 0..NEDGE-1
    int s = gid >> 18, e = gid & (EE - 1);
    int dst = adj_idx[(size_t)s * 2 * EE + e];
    atomicAdd(&g_deg[s * NN + dst], 1);
}

__global__ void scan1_kernel() {                 // 192 blocks x 1024
    __shared__ int tmp[1024];
    int tid = threadIdx.x;
    int gid = blockIdx.x * 1024 + tid;
    int x = g_deg[gid];
    tmp[tid] = x;
    __syncthreads();
#pragma unroll
    for (int d = 1; d < 1024; d <<= 1) {
        int t = (tid >= d) ? tmp[tid - d] : 0;
        __syncthreads();
        tmp[tid] += t;
        __syncthreads();
    }
    g_off[gid] = tmp[tid] - x;                   // exclusive
    if (tid == 1023) g_bsum[blockIdx.x] = tmp[tid];
}

__global__ void scan2_kernel() {                 // 1 block x 256
    __shared__ int tmp[256];
    int tid = threadIdx.x;
    int x = (tid < 192) ? g_bsum[tid] : 0;
    tmp[tid] = x;
    __syncthreads();
#pragma unroll
    for (int d = 1; d < 256; d <<= 1) {
        int t = (tid >= d) ? tmp[tid - d] : 0;
        __syncthreads();
        tmp[tid] += t;
        __syncthreads();
    }
    if (tid < 192) g_bsum[tid] = tmp[tid] - x;   // exclusive
}

__global__ void scan3_kernel() {                 // 192 blocks x 1024
    int gid = blockIdx.x * 1024 + threadIdx.x;
    int v = g_off[gid] + g_bsum[blockIdx.x];
    g_off[gid] = v;
    g_cur[gid] = v;
}

__global__ void fill_kernel(const int* __restrict__ adj_idx,
                            const float* __restrict__ adj_val) {
    int gid = blockIdx.x * 1024 + threadIdx.x;
    int s = gid >> 18, e = gid & (EE - 1);
    const int* ib = adj_idx + (size_t)s * 2 * EE;
    int dst = ib[e];
    int src = ib[EE + e];
    float v  = adj_val[(size_t)s * EE + e];
    int pos = atomicAdd(&g_cur[s * NN + dst], 1);
    g_epack[pos] = make_int2(src, __float_as_int(v));
}

// ============================================================
// gather: acc[row] = sum_e val[e] * support[src[e]]
// ============================================================
__global__ void __launch_bounds__(256)
gather_kernel() {
    int wid  = blockIdx.x * 8 + (threadIdx.x >> 5);   // row id
    int lane = threadIdx.x & 31;
    int s = wid >> 14;                                // NN = 2^14

    int start = g_off[wid];
    int cnt   = g_deg[wid];

    const int2*  epk  = g_epack + start;
    const float* supp = g_support + (size_t)s * NN * D + lane * 4;

    float ax = 0.f, ay = 0.f, az = 0.f, aw = 0.f;
    int i = 0;
    for (; i + 4 <= cnt; i += 4) {
        int2 p0 = __ldg(&epk[i + 0]);
        int2 p1 = __ldg(&epk[i + 1]);
        int2 p2 = __ldg(&epk[i + 2]);
        int2 p3 = __ldg(&epk[i + 3]);
        float4 m0 = *(const float4*)(supp + (size_t)p0.x * D);
        float4 m1 = *(const float4*)(supp + (size_t)p1.x * D);
        float4 m2 = *(const float4*)(supp + (size_t)p2.x * D);
        float4 m3 = *(const float4*)(supp + (size_t)p3.x * D);
        float v0 = __int_as_float(p0.y), v1 = __int_as_float(p1.y);
        float v2 = __int_as_float(p2.y), v3 = __int_as_float(p3.y);
        ax += v0 * m0.x; ay += v0 * m0.y; az += v0 * m0.z; aw += v0 * m0.w;
        ax += v1 * m1.x; ay += v1 * m1.y; az += v1 * m1.z; aw += v1 * m1.w;
        ax += v2 * m2.x; ay += v2 * m2.y; az += v2 * m2.z; aw += v2 * m2.w;
        ax += v3 * m3.x; ay += v3 * m3.y; az += v3 * m3.z; aw += v3 * m3.w;
    }
    for (; i < cnt; ++i) {
        int2 p = __ldg(&epk[i]);
        float v = __int_as_float(p.y);
        float4 m = *(const float4*)(supp + (size_t)p.x * D);
        ax += v * m.x; ay += v * m.y; az += v * m.z; aw += v * m.w;
    }
    *(float4*)(g_acc + (size_t)wid * D + lane * 4) = make_float4(ax, ay, az, aw);
}

// ============================================================
// K1: support = xs @ gcn_weight (256 threads, 8x8 reg tile)
// ============================================================
__global__ void __launch_bounds__(256)
support_kernel(const float* __restrict__ X, const float* __restrict__ W) {
    extern __shared__ float sm[];
    float* As = sm;                 // [64][132]  (As[k][r])
    float* Bs = sm + 64 * 132;      // [64][132]  (Bs[k][c])

    int tid = threadIdx.x;
    int tx = tid & 15, ty = tid >> 4;
    size_t rowbase = (size_t)blockIdx.x * 128;

    u64 accp[8][4];
#pragma unroll
    for (int i = 0; i < 8; ++i)
#pragma unroll
        for (int jj = 0; jj < 4; ++jj) accp[i][jj] = 0ull;

    for (int k0 = 0; k0 < 128; k0 += 64) {
        __syncthreads();
        for (int idx = tid; idx < 128 * 64; idx += 256) {
            int r = idx >> 6, k = idx & 63;
            As[k * 132 + r] = X[(rowbase + r) * 128 + k0 + k];
        }
        for (int idx = tid; idx < 64 * 128; idx += 256) {
            int k = idx >> 7, c = idx & 127;
            Bs[k * 132 + c] = W[(size_t)(k0 + k) * 128 + c];
        }
        __syncthreads();
#pragma unroll
        for (int k = 0; k < 64; ++k) {
            ulonglong2 b0 = *(const ulonglong2*)&Bs[k * 132 + tx * 4];
            ulonglong2 b1 = *(const ulonglong2*)&Bs[k * 132 + 64 + tx * 4];
            float4 a0 = *(const float4*)&As[k * 132 + ty * 4];
            float4 a1 = *(const float4*)&As[k * 132 + 64 + ty * 4];
            float af[8] = {a0.x,a0.y,a0.z,a0.w,a1.x,a1.y,a1.z,a1.w};
#pragma unroll
            for (int i = 0; i < 8; ++i) {
                u64 ap = bcast2(af[i]);
                ffma2(accp[i][0], ap, b0.x, accp[i][0]);
                ffma2(accp[i][1], ap, b0.y, accp[i][1]);
                ffma2(accp[i][2], ap, b1.x, accp[i][2]);
                ffma2(accp[i][3], ap, b1.y, accp[i][3]);
            }
        }
    }
#pragma unroll
    for (int i = 0; i < 8; ++i) {
        int r = (i < 4) ? (ty * 4 + i) : (64 + ty * 4 + i - 4);
        float* crow = g_support + (rowbase + r) * 128;
        float2 v0 = unpack2(accp[i][0]), v1 = unpack2(accp[i][1]);
        float2 v2 = unpack2(accp[i][2]), v3 = unpack2(accp[i][3]);
        *(float4*)&crow[tx * 4]      = make_float4(v0.x, v0.y, v1.x, v1.y);
        *(float4*)&crow[64 + tx * 4] = make_float4(v2.x, v2.y, v3.x, v3.y);
    }
}

// ============================================================
// gatesx part A: rb < TSPLIT/2 (timesteps < TSPLIT)
// grid (512, 4), 256 threads, 8x8 reg tile
// ============================================================
__global__ void __launch_bounds__(256)
gatesxA_kernel(const float* __restrict__ wih, const float* __restrict__ gcn_bias) {
    extern __shared__ float sm[];
    float* As = sm;                 // [64][132]  As[k][r] = relu(acc+b)
    float* Bs = sm + 64 * 132;      // [64][132]  Bs[k][c] = wih[cb*128+c][k]

    int tid = threadIdx.x;
    int tx = tid & 15, ty = tid >> 4;
    size_t rowbase = (size_t)blockIdx.x * 128;
    int cb = blockIdx.y;

    u64 accp[8][4];
#pragma unroll
    for (int i = 0; i < 8; ++i)
#pragma unroll
        for (int jj = 0; jj < 4; ++jj) accp[i][jj] = 0ull;

    for (int k0 = 0; k0 < 128; k0 += 64) {
        __syncthreads();
        for (int idx = tid; idx < 128 * 64; idx += 256) {
            int r = idx >> 6, k = idx & 63;
            float x = g_acc[(rowbase + r) * 128 + k0 + k] + __ldg(&gcn_bias[k0 + k]);
            As[k * 132 + r] = fmaxf(x, 0.f);
        }
        for (int idx = tid; idx < 128 * 64; idx += 256) {     // idx = c*64 + k
            int c = idx >> 6, k = idx & 63;
            Bs[k * 132 + c] = wih[((size_t)(cb * 128 + c)) * 128 + k0 + k];
        }
        __syncthreads();
#pragma unroll
        for (int k = 0; k < 64; ++k) {
            ulonglong2 b0 = *(const ulonglong2*)&Bs[k * 132 + tx * 4];
            ulonglong2 b1 = *(const ulonglong2*)&Bs[k * 132 + 64 + tx * 4];
            float4 a0 = *(const float4*)&As[k * 132 + ty * 4];
            float4 a1 = *(const float4*)&As[k * 132 + 64 + ty * 4];
            float af[8] = {a0.x,a0.y,a0.z,a0.w,a1.x,a1.y,a1.z,a1.w};
#pragma unroll
            for (int i = 0; i < 8; ++i) {
                u64 ap = bcast2(af[i]);
                ffma2(accp[i][0], ap, b0.x, accp[i][0]);
                ffma2(accp[i][1], ap, b0.y, accp[i][1]);
                ffma2(accp[i][2], ap, b1.x, accp[i][2]);
                ffma2(accp[i][3], ap, b1.y, accp[i][3]);
            }
        }
    }
#pragma unroll
    for (int i = 0; i < 8; ++i) {
        int r = (i < 4) ? (ty * 4 + i) : (64 + ty * 4 + i - 4);
        float* crow = g_gx + (rowbase + r) * 512 + cb * 128;
        float2 v0 = unpack2(accp[i][0]), v1 = unpack2(accp[i][1]);
        float2 v2 = unpack2(accp[i][2]), v3 = unpack2(accp[i][3]);
        *(float4*)&crow[tx * 4]      = make_float4(v0.x, v0.y, v1.x, v1.y);
        *(float4*)&crow[64 + tx * 4] = make_float4(v2.x, v2.y, v3.x, v3.y);
    }
}

// ============================================================
// LSTM chain over [t0, t1), one CTA per batch lane, 512 thr.
// Saves h/c state to device globals at the end.
// ============================================================
__device__ __forceinline__ void lstm_chain(
    int b, int t0, int t1,
    const float* __restrict__ hin, const float* __restrict__ cin,
    const float* __restrict__ whh, const float* __restrict__ bih,
    const float* __restrict__ bhh, float* __restrict__ out)
{
    extern __shared__ float sm[];
    float* sW32 = sm;                 // [512][36]: whh[j][k], k<32
    float* sH   = sm + 512 * 36;      // [128]
    float* sC   = sH + 128;           // [128]
    float* sG   = sC + 128;           // [512]
    int j = threadIdx.x;
    int gate = j >> 7;                // 0:i 1:f 2:g 3:o

    for (int idx = j; idx < 512 * 32; idx += 512) {
        int jj = idx >> 5, k = idx & 31;
        sW32[jj * 36 + k] = whh[(size_t)jj * 128 + k];
    }
    u64 wreg2[48];                    // k in [32,128), packed pairs
#pragma unroll
    for (int k = 0; k < 48; ++k)
        wreg2[k] = *(const u64*)&whh[(size_t)j * 128 + 32 + 2 * k];

    if (j < 128) {
        sH[j] = hin[b * 128 + j];
        sC[j] = cin[b * 128 + j];
    }
    float bias = bih[j] + bhh[j];
    __syncthreads();

    const float* gxp = g_gx + (size_t)b * 512 + j;
    float gx_cur = gxp[(size_t)t0 * 32768];

    for (int t = t0; t < t1; ++t) {
        float gx_next = (t + 1 < t1) ? gxp[(size_t)(t + 1) * 32768] : 0.f;

        u64 a0 = 0ull, a1 = 0ull, a2 = 0ull, a3 = 0ull;
        const float* wrow = &sW32[j * 36];
#pragma unroll
        for (int k = 0; k < 32; k += 4) {
            ulonglong2 w = *(const ulonglong2*)&wrow[k];
            ulonglong2 h = *(const ulonglong2*)&sH[k];
            ffma2(a0, h.x, w.x, a0);
            ffma2(a1, h.y, w.y, a1);
        }
#pragma unroll
        for (int k = 0; k < 96; k += 8) {
            ulonglong2 hA = *(const ulonglong2*)&sH[32 + k];
            ulonglong2 hB = *(const ulonglong2*)&sH[36 + k];
            ffma2(a2, hA.x, wreg2[k / 2 + 0], a2);
            ffma2(a3, hA.y, wreg2[k / 2 + 1], a3);
            ffma2(a0, hB.x, wreg2[k / 2 + 2], a0);
            ffma2(a1, hB.y, wreg2[k / 2 + 3], a1);
        }
        float2 p0 = unpack2(a0), p1 = unpack2(a1);
        float2 p2 = unpack2(a2), p3 = unpack2(a3);
        float pre = (((p0.x + p0.y) + (p1.x + p1.y)) +
                     ((p2.x + p2.y) + (p3.x + p3.y))) + gx_cur + bias;
        sG[j] = (gate == 2) ? ftanh(pre) : fsigm(pre);
        __syncthreads();

        if (j < 128) {
            float c = sG[128 + j] * sC[j] + sG[j] * sG[256 + j];
            sC[j] = c;
            float h = sG[384 + j] * ftanh(c);
            sH[j] = h;
            out[((size_t)t * 64 + b) * 128 + j] = h;
        }
        __syncthreads();
        gx_cur = gx_next;
    }

    if (j < 128) {
        g_hstate[b * 128 + j] = sH[j];
        g_cstate[b * 128 + j] = sC[j];
    }
}

// ============================================================
// COMBO kernel: 148 CTAs x 512 threads, NO cross-CTA comms.
//  CTA 0..63   : LSTM for t in [0, TSPLIT)  (gx already complete
//                for these rows from gatesxA_kernel)
//  CTA 64..147 : gates_x producer for items [ITEM_OFS, NITEMS_TOT)
//                (gx rows the LSTM in THIS launch never reads)
// ============================================================
__global__ void __launch_bounds__(512, 1)
combo_kernel(const float* __restrict__ wih,  const float* __restrict__ gb,
             const float* __restrict__ whh,
             const float* __restrict__ bih,  const float* __restrict__ bhh,
             const float* __restrict__ h0,   const float* __restrict__ c0,
             float* __restrict__ out) {
    if (blockIdx.x < 64) {
        lstm_chain(blockIdx.x, 0, TSPLIT, h0, c0, whh, bih, bhh, out);
        return;
    }

    // ---------- producer: gates_x for rb >= TSPLIT/2 ----------
    extern __shared__ float sm[];
    float* As = sm;                 // [64][132]
    float* Bs = sm + 64 * 132;      // [64][132]
    __shared__ int sItem;
    int tid = threadIdx.x;
    int tx = tid & 15, ty = tid >> 4;       // ty 0..31 -> 4 rows each

    for (;;) {
        if (tid == 0) sItem = ITEM_OFS + atomicAdd(&g_ticket, 1);
        __syncthreads();
        int item = sItem;
        if (item >= NITEMS_TOT) break;
        int rb = item >> 2, cb = item & 3;
        size_t rowbase = (size_t)rb * 128;

        u64 accp[4][4];
#pragma unroll
        for (int i = 0; i < 4; ++i)
#pragma unroll
            for (int jj = 0; jj < 4; ++jj) accp[i][jj] = 0ull;

        for (int k0 = 0; k0 < 128; k0 += 64) {
            __syncthreads();
            for (int idx = tid; idx < 128 * 64; idx += 512) {
                int r = idx >> 6, k = idx & 63;
                float x = g_acc[(rowbase + r) * 128 + k0 + k] + __ldg(&gb[k0 + k]);
                As[k * 132 + r] = fmaxf(x, 0.f);
            }
            for (int idx = tid; idx < 128 * 64; idx += 512) {
                int c = idx >> 6, k = idx & 63;
                Bs[k * 132 + c] = wih[((size_t)(cb * 128 + c)) * 128 + k0 + k];
            }
            __syncthreads();
#pragma unroll
            for (int k = 0; k < 64; ++k) {
                ulonglong2 b0 = *(const ulonglong2*)&Bs[k * 132 + tx * 4];
                ulonglong2 b1 = *(const ulonglong2*)&Bs[k * 132 + 64 + tx * 4];
                float4 a = *(const float4*)&As[k * 132 + ty * 4];
                float af[4] = {a.x, a.y, a.z, a.w};
#pragma unroll
                for (int i = 0; i < 4; ++i) {
                    u64 ap = bcast2(af[i]);
                    ffma2(accp[i][0], ap, b0.x, accp[i][0]);
                    ffma2(accp[i][1], ap, b0.y, accp[i][1]);
                    ffma2(accp[i][2], ap, b1.x, accp[i][2]);
                    ffma2(accp[i][3], ap, b1.y, accp[i][3]);
                }
            }
        }
#pragma unroll
        for (int i = 0; i < 4; ++i) {
            float* crow = g_gx + (rowbase + ty * 4 + i) * 512 + cb * 128;
            float2 v0 = unpack2(accp[i][0]), v1 = unpack2(accp[i][1]);
            float2 v2 = unpack2(accp[i][2]), v3 = unpack2(accp[i][3]);
            *(float4*)&crow[tx * 4]      = make_float4(v0.x, v0.y, v1.x, v1.y);
            *(float4*)&crow[64 + tx * 4] = make_float4(v2.x, v2.y, v3.x, v3.y);
        }
        // next loop's top __syncthreads separates these stores'
        // smem reuse; gx consumers are in a LATER kernel launch.
    }
}

// ============================================================
// LSTM part B: t in [TSPLIT, TT), state from device globals
// ============================================================
__global__ void __launch_bounds__(512, 1)
lstm2_kernel(const float* __restrict__ whh,
             const float* __restrict__ bih, const float* __restrict__ bhh,
             float* __restrict__ out) {
    lstm_chain(blockIdx.x, TSPLIT, TT, g_hstate, g_cstate, whh, bih, bhh, out);
}

// ============================================================
// launch
// ============================================================
extern "C" void kernel_launch(void* const* d_in, const int* in_sizes, int n_in,
                              void* d_out, int out_size) {
    const int*   adj_idx = (const int*)  d_in[0];
    const float* adj_val = (const float*)d_in[1];
    const float* xs      = (const float*)d_in[2];
    const float* gw      = (const float*)d_in[3];
    const float* gb      = (const float*)d_in[4];
    const float* wih     = (const float*)d_in[5];
    const float* whh     = (const float*)d_in[6];
    const float* bih     = (const float*)d_in[7];
    const float* bhh     = (const float*)d_in[8];
    const float* h0      = (const float*)d_in[9];
    const float* c0      = (const float*)d_in[10];
    float* out = (float*)d_out;

    (void)in_sizes; (void)n_in; (void)out_size;

    const int GEMM_SMEM  = 2 * 64 * 132 * 4;                        // 67584
    const int FUSED_SMEM = (512 * 36 + 128 + 128 + 512) * 4;        // 76800

    static bool attr_done = false;
    if (!attr_done) {
        cudaFuncSetAttribute(support_kernel, cudaFuncAttributeMaxDynamicSharedMemorySize, GEMM_SMEM);
        cudaFuncSetAttribute(gatesxA_kernel, cudaFuncAttributeMaxDynamicSharedMemorySize, GEMM_SMEM);
        cudaFuncSetAttribute(combo_kernel,   cudaFuncAttributeMaxDynamicSharedMemorySize, FUSED_SMEM);
        cudaFuncSetAttribute(lstm2_kernel,   cudaFuncAttributeMaxDynamicSharedMemorySize, FUSED_SMEM);
        attr_done = true;
    }

    // init + CSR build
    init_kernel<<<192, 1024>>>();
    hist_kernel<<<NEDGE / 1024, 1024>>>(adj_idx);
    scan1_kernel<<<192, 1024>>>();
    scan2_kernel<<<1, 256>>>();
    scan3_kernel<<<192, 1024>>>();
    fill_kernel<<<NEDGE / 1024, 1024>>>(adj_idx, adj_val);

    // support GEMM
    support_kernel<<<1536, 256, GEMM_SMEM>>>(xs, gw);

    // gather
    gather_kernel<<<ROWS / 8, 256>>>();

    // gates_x for t < TSPLIT (rb < 512)
    gatesxA_kernel<<<dim3(TSPLIT / 2, 4), 256, GEMM_SMEM>>>(wih, gb);

    // overlap: LSTM[0,TSPLIT) on 64 CTAs || gates_x rb>=512 on 84 CTAs
    combo_kernel<<<148, 512, FUSED_SMEM>>>(wih, gb, whh, bih, bhh, h0, c0, out);

    // LSTM [TSPLIT, TT)
    lstm2_kernel<<<64, 512, FUSED_SMEM>>>(whh, bih, bhh, out);
}